// round 16
// baseline (speedup 1.0000x reference)
#include <cuda_runtime.h>
#include <cuda_bf16.h>
#include <math.h>

#define NP      147456      // 16*96*96
#define HW      9216        // 96*96
#define CDIM    512
#define KP      64          // protos per side
#define NSEL    256
#define NREF    10
#define TAU     0.07f
#define MARGIN  0.2f
#define MBLEND  0.3f

#define NCAND   2048        // approx-candidate target per side
#define CAP     4096        // candidate buffer cap (whole boundary bin included)

// ---------------- scratch ----------------
__device__ float     g_Wt[CDIM * 128];
__device__ unsigned  g_Wb16u[128 * 256];
__device__ float     g_score[2][NP];
__device__ unsigned  g_hist16[2][65536];
__device__ int       g_thr16[2];
__device__ int       g_ccnt[2];
__device__ int       g_cand[2][CAP];
__device__ float     g_cscore[2][CAP];
__device__ int       g_idx[2][NSEL];
__device__ float     g_feats[2][NSEL * CDIM];
__device__ float     g_p[2][KP * CDIM];
__device__ int       g_assign[2][NSEL];
__device__ unsigned long long g_lossacc[3];
__device__ int       g_losscnt;

// ---------------- helpers ----------------
__device__ __forceinline__ unsigned mapf(float x) {
    unsigned u = __float_as_uint(x);
    return (u & 0x80000000u) ? ~u : (u | 0x80000000u);
}
__device__ __forceinline__ unsigned pack_bf2(float lo, float hi) {
    unsigned r;
    asm("cvt.rn.bf16x2.f32 %0, %1, %2;" : "=r"(r) : "f"(hi), "f"(lo));
    return r;
}
__device__ __forceinline__ void mma16816(float* c, const unsigned* a, unsigned b0, unsigned b1) {
    asm volatile("mma.sync.aligned.m16n8k16.row.col.f32.bf16.bf16.f32 "
                 "{%0,%1,%2,%3}, {%4,%5,%6,%7}, {%8,%9}, {%0,%1,%2,%3};"
                 : "+f"(c[0]), "+f"(c[1]), "+f"(c[2]), "+f"(c[3])
                 : "r"(a[0]), "r"(a[1]), "r"(a[2]), "r"(a[3]), "r"(b0), "r"(b1));
}
__device__ __forceinline__ unsigned sptr(const void* p) {
    return (unsigned)__cvta_generic_to_shared(p);
}
__device__ __forceinline__ void cp16_cg(unsigned s, const void* g) {
    asm volatile("cp.async.cg.shared.global [%0], [%1], 16;" :: "r"(s), "l"(g));
}
__device__ __forceinline__ void cp16_ca(unsigned s, const void* g) {
    asm volatile("cp.async.ca.shared.global [%0], [%1], 16;" :: "r"(s), "l"(g));
}

// ---------------- kernel 1: fused prep ----------------
__global__ void prep_all(const float* __restrict__ fg, const float* __restrict__ bg) {
    int gid = blockIdx.x * 256 + threadIdx.x;   // 65536 threads
    ((unsigned*)&g_hist16[0][0])[gid] = 0u;
    ((unsigned*)&g_hist16[0][0])[gid + 65536] = 0u;
    if (gid < 2) g_ccnt[gid] = 0;
    if (gid < 3) g_lossacc[gid] = 0ULL;
    if (gid == 0) g_losscnt = 0;
    {
        int c = gid >> 7, j = gid & 127;
        float v = (j < KP) ? fg[j * CDIM + c] : bg[(j - KP) * CDIM + c];
        g_Wt[gid] = v;
    }
    if (gid < 32768) {
        int j = gid >> 8, cp = gid & 255;
        const float* src = (j < KP) ? (fg + j * CDIM) : (bg + (j - KP) * CDIM);
        g_Wb16u[gid] = pack_bf2(src[cp * 2], src[cp * 2 + 1]);
    }
}

// ---------------- kernel 2: approx score (bf16 TC) + fused hist16 ----------------
#define SCORE_SMEM (32768 + 20480 + 10240 + 512)
__global__ __launch_bounds__(256, 2) void score_tc(
    const float* __restrict__ F, const float* __restrict__ M) {
    extern __shared__ char smem_raw[];
    float*    Af32   = (float*)smem_raw;
    unsigned* Wst    = (unsigned*)(smem_raw + 32768);
    unsigned* As32   = (unsigned*)(smem_raw + 32768 + 20480);
    float*    normsh = (float*)(smem_raw + 63488);

    int tid = threadIdx.x, lane = tid & 31, w = tid >> 5;
    int wm = w >> 1, wn = w & 1;
    int gpix0 = blockIdx.x * 128;
    int n = gpix0 / HW, hw0 = gpix0 - n * HW;
    const float* Fb = F + (size_t)n * CDIM * HW + hw0;

    if (tid < 128) normsh[tid] = 0.f;

    float acc[2][8][4];
#pragma unroll
    for (int a = 0; a < 2; a++)
#pragma unroll
        for (int b = 0; b < 8; b++)
#pragma unroll
            for (int d = 0; d < 4; d++) acc[a][b][d] = 0.f;

    int px = tid & 127, half = tid >> 7;
    float mynrm = 0.f;

    auto issue_chunk = [&](int ic) {
        int buf = ic & 1;
        int c0 = ic * 32;
        float* Ad = Af32 + buf * (32 * 128);
#pragma unroll
        for (int j = 0; j < 4; j++) {
            int idx = tid + 256 * j;
            int r = idx >> 5, sg = idx & 31;
            cp16_cg(sptr(Ad + r * 128 + sg * 4),
                    Fb + (size_t)(c0 + r) * HW + sg * 4);
        }
        unsigned* Wd = Wst + buf * (128 * 20);
#pragma unroll
        for (int j = 0; j < 2; j++) {
            int idx = tid + 256 * j;
            int p = idx >> 2, sg = idx & 3;
            cp16_ca(sptr(Wd + p * 20 + sg * 4),
                    g_Wb16u + p * 256 + (c0 >> 1) + sg * 4);
        }
        asm volatile("cp.async.commit_group;");
    };

    issue_chunk(0);
    issue_chunk(1);

    int g = lane >> 2, t4 = lane & 3;
    for (int ic = 0; ic < 16; ic++) {
        int buf = ic & 1;
        if (ic < 15) asm volatile("cp.async.wait_group 1;");
        else         asm volatile("cp.async.wait_group 0;");
        __syncthreads();

        {
            const float* Asrc = Af32 + buf * (32 * 128);
#pragma unroll
            for (int kp = 0; kp < 8; kp++) {
                int k = (half * 8 + kp) * 2;
                float v0 = Asrc[k * 128 + px];
                float v1 = Asrc[(k + 1) * 128 + px];
                mynrm += v0 * v0 + v1 * v1;
                As32[px * 20 + half * 8 + kp] = pack_bf2(v0, v1);
            }
        }
        __syncthreads();

        {
            const unsigned* Ws = Wst + buf * (128 * 20);
#pragma unroll
            for (int k16 = 0; k16 < 2; k16++) {
                unsigned a[2][4];
#pragma unroll
                for (int mt = 0; mt < 2; mt++) {
                    int row = wm * 32 + mt * 16 + g;
                    int base = row * 20 + k16 * 8 + t4;
                    a[mt][0] = As32[base];
                    a[mt][1] = As32[base + 8 * 20];
                    a[mt][2] = As32[base + 4];
                    a[mt][3] = As32[base + 8 * 20 + 4];
                }
#pragma unroll
                for (int nt = 0; nt < 8; nt++) {
                    int pr = wn * 64 + nt * 8 + g;
                    int bb = pr * 20 + k16 * 8 + t4;
                    unsigned b0 = Ws[bb], b1 = Ws[bb + 4];
#pragma unroll
                    for (int mt = 0; mt < 2; mt++) mma16816(acc[mt][nt], a[mt], b0, b1);
                }
            }
        }
        __syncthreads();
        if (ic + 2 < 16) issue_chunk(ic + 2);
    }

    atomicAdd(&normsh[px], mynrm);
    __syncthreads();

#pragma unroll
    for (int mt = 0; mt < 2; mt++) {
#pragma unroll
        for (int h = 0; h < 2; h++) {
            float m = -1e30f;
#pragma unroll
            for (int nt = 0; nt < 8; nt++)
                m = fmaxf(m, fmaxf(acc[mt][nt][h * 2], acc[mt][nt][h * 2 + 1]));
            m = fmaxf(m, __shfl_xor_sync(0xFFFFFFFFu, m, 1));
            m = fmaxf(m, __shfl_xor_sync(0xFFFFFFFFu, m, 2));
            if ((lane & 3) == 0) {
                int p = wm * 32 + mt * 16 + h * 8 + g;
                float inv = 1.0f / fmaxf(sqrtf(normsh[p]), 1e-8f);
                float sim = m * inv;
                float mv = fminf(fmaxf(M[gpix0 + p], 0.f), 1.f);
                float d = 1.0f - sim;
                float sc = (wn == 0) ? d * mv : d * (1.0f - mv);
                g_score[wn][gpix0 + p] = sc;
                atomicAdd(&g_hist16[wn][mapf(sc) >> 16], 1u);   // fused hist16
            }
        }
    }
}

// ---------------- kernel 3: pick 16-bit threshold (parallel suffix-scan) ----------------
__global__ void pick16_kernel() {
    int side = blockIdx.x, tid = threadIdx.x;   // 256 threads
    __shared__ unsigned ps[256];
    __shared__ unsigned suf[256];
    __shared__ int sh_seg;

    {
        const uint4* h4 = (const uint4*)&g_hist16[side][tid * 256];
        unsigned s = 0;
#pragma unroll 16
        for (int i = 0; i < 64; i++) {
            uint4 v = h4[i];
            s += v.x + v.y + v.z + v.w;
        }
        ps[tid] = s;
    }
    __syncthreads();
    for (int o = 1; o < 256; o <<= 1) {
        unsigned add = (tid + o < 256) ? ps[tid + o] : 0u;
        __syncthreads();
        ps[tid] += add;
        __syncthreads();
    }
    if (ps[tid] >= (unsigned)NCAND && (tid == 255 || ps[tid + 1] < (unsigned)NCAND))
        sh_seg = tid;
    __syncthreads();
    int seg = sh_seg;
    unsigned segAbove = (seg == 255) ? 0u : ps[seg + 1];

    suf[tid] = g_hist16[side][seg * 256 + tid];
    __syncthreads();
    for (int o = 1; o < 256; o <<= 1) {
        unsigned add = (tid + o < 256) ? suf[tid + o] : 0u;
        __syncthreads();
        suf[tid] += add;
        __syncthreads();
    }
    unsigned need = (unsigned)NCAND - segAbove;
    if (suf[tid] >= need && (tid == 255 || suf[tid + 1] < need))
        g_thr16[side] = seg * 256 + tid;
}

// ---------------- kernel 4: collect candidates (16-bit threshold, superset) ----------------
__global__ void collect_kernel() {
    int side = blockIdx.y;
    int i = blockIdx.x * 256 + threadIdx.x;
    unsigned key16 = mapf(g_score[side][i]) >> 16;
    if ((int)key16 >= g_thr16[side]) {
        int pos = atomicAdd(&g_ccnt[side], 1);
        if (pos < CAP) g_cand[side][pos] = i;
    }
}

// ---------------- kernel 5: exact FP32 rescore (16 candidates/block, verified) ----------------
__global__ __launch_bounds__(256) void rescore_kernel(
    const float* __restrict__ F, const float* __restrict__ M) {
    int side = blockIdx.y;
    int s0 = blockIdx.x * 16;
    int tid = threadIdx.x, lane = tid & 31, w = tid >> 5;
    int cnt = min(g_ccnt[side], CAP);

    if (s0 >= cnt) {
        if (tid < 16) g_cscore[side][s0 + tid] = -3.0e38f;
        return;
    }

    __shared__ float fsh[16][CDIM];
    __shared__ float nrm[16];

#pragma unroll
    for (int h = 0; h < 2; h++) {
        int cslot = 2 * w + h;
        int s = s0 + cslot;
        bool valid = (s < cnt);
        int idx = g_cand[side][valid ? s : 0];
        int n = idx / HW, hw = idx - n * HW;
        const float* base = F + (size_t)n * CDIM * HW + hw;
        float partial = 0.f;
#pragma unroll
        for (int i = 0; i < 16; i++) {
            int c = lane + 32 * i;
            float v = base[(size_t)c * HW];
            fsh[cslot][c] = v;
            partial += v * v;
        }
#pragma unroll
        for (int o = 16; o > 0; o >>= 1)
            partial += __shfl_xor_sync(0xFFFFFFFFu, partial, o);
        if (lane == 0) nrm[cslot] = partial;
    }
    __syncthreads();

    int half = lane >> 4, l16 = lane & 15;
    int cslot = 2 * w + half;
    const float* Wb = g_Wt + side * 64 + l16 * 4;
    float d0 = 0.f, d1 = 0.f, d2 = 0.f, d3 = 0.f;
#pragma unroll 4
    for (int c = 0; c < CDIM; c++) {
        float f = fsh[cslot][c];
        float4 wv = *(const float4*)(Wb + (size_t)c * 128);
        d0 = fmaf(f, wv.x, d0);
        d1 = fmaf(f, wv.y, d1);
        d2 = fmaf(f, wv.z, d2);
        d3 = fmaf(f, wv.w, d3);
    }
    float m = fmaxf(fmaxf(d0, d1), fmaxf(d2, d3));
#pragma unroll
    for (int o = 8; o > 0; o >>= 1)
        m = fmaxf(m, __shfl_xor_sync(0xFFFFFFFFu, m, o));
    if (l16 == 0) {
        int s = s0 + cslot;
        bool valid = (s < cnt);
        float val = -3.0e38f;
        if (valid) {
            int idx = g_cand[side][s];
            float inv = 1.0f / fmaxf(sqrtf(nrm[cslot]), 1e-8f);
            float sim = m * inv;
            float mv = fminf(fmaxf(M[idx], 0.f), 1.f);
            val = (side == 0) ? (1.0f - sim) * mv : (1.0f - sim) * (1.0f - mv);
        }
        g_cscore[side][s] = val;
    }
}

// ---------------- kernel 6: exact top-256 among candidates ----------------
__global__ void select256_kernel() {
    int side = blockIdx.x, tid = threadIdx.x;   // 256 threads
    const float* sc = g_cscore[side];
    const int* cd = g_cand[side];
    __shared__ unsigned hist[256];
    __shared__ unsigned suf[256];
    __shared__ unsigned sh_pfx, sh_dmask;
    __shared__ int sh_krem, gcnt, tcnt;
    __shared__ int glist[NSEL];
    __shared__ int ties[CAP];

    if (tid == 0) { sh_pfx = 0; sh_dmask = 0; sh_krem = NSEL; }
    __syncthreads();
    for (int shift = 24; shift >= 0; shift -= 8) {
        hist[tid] = 0;
        __syncthreads();
        unsigned dm = sh_dmask, pf = sh_pfx;
        for (int i = tid; i < CAP; i += 256) {
            unsigned key = mapf(sc[i]);
            if ((key & dm) == pf) atomicAdd(&hist[(key >> shift) & 255], 1u);
        }
        __syncthreads();
        suf[tid] = hist[tid];
        __syncthreads();
        for (int o = 1; o < 256; o <<= 1) {
            unsigned add = (tid + o < 256) ? suf[tid + o] : 0u;
            __syncthreads();
            suf[tid] += add;
            __syncthreads();
        }
        unsigned kr = (unsigned)sh_krem;
        if (suf[tid] >= kr && (tid == 255 || suf[tid + 1] < kr)) {
            sh_krem = (int)kr - (int)((tid == 255) ? 0u : suf[tid + 1]);
            sh_pfx   = sh_pfx | ((unsigned)tid << shift);
            sh_dmask = sh_dmask | (0xFFu << shift);
        }
        __syncthreads();
    }
    if (tid == 0) { gcnt = 0; tcnt = 0; }
    __syncthreads();
    unsigned thr = sh_pfx;
    for (int i = tid; i < CAP; i += 256) {
        unsigned key = mapf(sc[i]);
        if (key > thr) {
            int p = atomicAdd(&gcnt, 1);
            if (p < NSEL) glist[p] = cd[i];
        } else if (key == thr) {
            int p = atomicAdd(&tcnt, 1);
            if (p < CAP) ties[p] = cd[i];
        }
    }
    __syncthreads();
    int G = min(gcnt, NSEL);
    for (int e = tid; e < G; e += 256) {
        int pe = glist[e], r = 0;
        for (int j = 0; j < G; j++) r += (glist[j] < pe);
        g_idx[side][r] = pe;
    }
    int need = NSEL - G;
    int T = min(tcnt, CAP);
    for (int e = tid; e < T; e += 256) {
        int pe = ties[e], r = 0;
        for (int j = 0; j < T; j++) r += (ties[j] < pe);
        if (r < need) g_idx[side][G + r] = pe;
    }
}

// ---------------- kernel 7: gather + normalize + fused proto init ----------------
__global__ void gather_kernel(const float* __restrict__ F,
                              const float* __restrict__ fg, const float* __restrict__ bg) {
    int s = blockIdx.x, side = blockIdx.y;
    int idx = g_idx[side][s];
    int n = idx / HW, hw = idx - n * HW;
    const float* base = F + (size_t)n * CDIM * HW + hw;
    int tid = threadIdx.x;  // 128
    float v[4], ss = 0.f;
#pragma unroll
    for (int i = 0; i < 4; i++) {
        int c = tid + i * 128;
        v[i] = base[(size_t)c * HW];
        ss += v[i] * v[i];
    }
#pragma unroll
    for (int o = 16; o > 0; o >>= 1) ss += __shfl_xor_sync(0xFFFFFFFFu, ss, o);
    __shared__ float wsum[4];
    if ((tid & 31) == 0) wsum[tid >> 5] = ss;
    __syncthreads();
    float inv = 1.0f / fmaxf(sqrtf(wsum[0] + wsum[1] + wsum[2] + wsum[3]), 1e-8f);
#pragma unroll
    for (int i = 0; i < 4; i++)
        g_feats[side][s * CDIM + tid + i * 128] = v[i] * inv;
    // fused init_p: blocks s < KP copy proto row s
    if (s < KP) {
        const float* src = side ? bg : fg;
#pragma unroll
        for (int i = 0; i < 4; i++)
            g_p[side][s * CDIM + tid + i * 128] = src[s * CDIM + tid + i * 128];
    }
}

// ---------------- kernel 8: full refinement loop — ONE launch, cluster-synced ----------------
// grid 16 blocks x 512 threads; cluster size 8; blocks 0-7 = side 0, 8-15 = side 1.
// Each side's 10 iterations run inside one cluster with barrier.cluster between phases.
__global__ void __cluster_dims__(8, 1, 1) __launch_bounds__(512, 1)
refine_cluster() {
    int tid = threadIdx.x;
    int side  = blockIdx.x >> 3;
    int brank = blockIdx.x & 7;

    __shared__ float dsm[32][KP];   // 8 KB
    __shared__ int   asg[NSEL];     // 1 KB
    __shared__ float vbuf[512];     // 2 KB
    __shared__ float red[256];      // 1 KB

    int j  = tid & 63;              // proto for assign phase
    int sg = tid >> 6;              // 0..7 sample group
    int k0 = brank * 8;             // update: clusters k0..k0+7

    for (int it = 0; it < NREF; it++) {
        float step = 0.1f / (1.0f + 0.5f * (float)it);

        // ---- assign: samples brank*32 .. +31 ----
        {
            const float* pj = g_p[side] + j * CDIM;
            int sb = brank * 32 + sg * 4;
            const float* f0 = g_feats[side] + (size_t)(sb + 0) * CDIM;
            const float* f1 = g_feats[side] + (size_t)(sb + 1) * CDIM;
            const float* f2 = g_feats[side] + (size_t)(sb + 2) * CDIM;
            const float* f3 = g_feats[side] + (size_t)(sb + 3) * CDIM;
            float d0 = 0.f, d1 = 0.f, d2 = 0.f, d3 = 0.f;
            for (int c = 0; c < CDIM; c += 4) {
                float4 pv = *(const float4*)(pj + c);
                float4 a0 = *(const float4*)(f0 + c);
                float4 a1 = *(const float4*)(f1 + c);
                float4 a2 = *(const float4*)(f2 + c);
                float4 a3 = *(const float4*)(f3 + c);
                d0 = fmaf(a0.x, pv.x, fmaf(a0.y, pv.y, fmaf(a0.z, pv.z, fmaf(a0.w, pv.w, d0))));
                d1 = fmaf(a1.x, pv.x, fmaf(a1.y, pv.y, fmaf(a1.z, pv.z, fmaf(a1.w, pv.w, d1))));
                d2 = fmaf(a2.x, pv.x, fmaf(a2.y, pv.y, fmaf(a2.z, pv.z, fmaf(a2.w, pv.w, d2))));
                d3 = fmaf(a3.x, pv.x, fmaf(a3.y, pv.y, fmaf(a3.z, pv.z, fmaf(a3.w, pv.w, d3))));
            }
            dsm[sg * 4 + 0][j] = d0;
            dsm[sg * 4 + 1][j] = d1;
            dsm[sg * 4 + 2][j] = d2;
            dsm[sg * 4 + 3][j] = d3;
            __syncthreads();
            if (tid < 32) {
                float best = dsm[tid][0];
                int bj = 0;
                for (int jj = 1; jj < KP; jj++) {
                    float v = dsm[tid][jj];
                    if (v > best) { best = v; bj = jj; }
                }
                g_assign[side][brank * 32 + tid] = bj;
            }
        }
        __threadfence();
        asm volatile("barrier.cluster.arrive.aligned;" ::: "memory");
        asm volatile("barrier.cluster.wait.aligned;"   ::: "memory");

        // ---- update: clusters k0..k0+7, channel c = tid ----
        {
            if (tid < 256) asg[tid] = g_assign[side][tid];
            __syncthreads();
            float a0 = 0.f, a1 = 0.f, a2 = 0.f, a3 = 0.f,
                  a4 = 0.f, a5 = 0.f, a6 = 0.f, a7 = 0.f;
            int c0 = 0, c1 = 0, c2 = 0, c3 = 0, c4 = 0, c5 = 0, c6 = 0, c7 = 0;
            for (int s = 0; s < NSEL; s++) {
                int rel = asg[s] - k0;
                float fv = 0.0f;
                if ((unsigned)rel < 8u) fv = g_feats[side][s * CDIM + tid];
                a0 += (rel == 0) ? fv : 0.0f;  c0 += (rel == 0);
                a1 += (rel == 1) ? fv : 0.0f;  c1 += (rel == 1);
                a2 += (rel == 2) ? fv : 0.0f;  c2 += (rel == 2);
                a3 += (rel == 3) ? fv : 0.0f;  c3 += (rel == 3);
                a4 += (rel == 4) ? fv : 0.0f;  c4 += (rel == 4);
                a5 += (rel == 5) ? fv : 0.0f;  c5 += (rel == 5);
                a6 += (rel == 6) ? fv : 0.0f;  c6 += (rel == 6);
                a7 += (rel == 7) ? fv : 0.0f;  c7 += (rel == 7);
            }
            float accq[8] = {a0, a1, a2, a3, a4, a5, a6, a7};
            int   cntq[8] = {c0, c1, c2, c3, c4, c5, c6, c7};
#pragma unroll
            for (int q = 0; q < 8; q++) {
                int k = k0 + q;
                int cnt = cntq[q];
                float denom = fmaxf((float)cnt, 1.0f);
                float p0 = g_p[side][k * CDIM + tid];
                float v = (1.0f - step) * p0 + step * (accq[q] / denom);
                vbuf[tid] = v;
                __syncthreads();
                if (tid < 256) {
                    float v0 = vbuf[tid], v1 = vbuf[tid + 256];
                    red[tid] = v0 * v0 + v1 * v1;
                }
                __syncthreads();
                for (int o = 128; o > 0; o >>= 1) {
                    if (tid < o) red[tid] += red[tid + o];
                    __syncthreads();
                }
                float inv = 1.0f / fmaxf(sqrtf(red[0]), 1e-8f);
                if (cnt > 0)
                    g_p[side][k * CDIM + tid] = v * inv;
                __syncthreads();
            }
        }
        __threadfence();
        asm volatile("barrier.cluster.arrive.aligned;" ::: "memory");
        asm volatile("barrier.cluster.wait.aligned;"   ::: "memory");
    }
}

// ---------------- kernel 9: loss (blocks 0-255) + refined output (blocks 256-383)
//                  + exact-integer atomic finalize ----------------
__global__ __launch_bounds__(256) void loss_final(
    const float* __restrict__ fg, const float* __restrict__ bg,
    float* __restrict__ out) {
    int b = blockIdx.x, tid = threadIdx.x;

    if (b < 256) {
        int s = b;
        __shared__ float posf[CDIM], negf[CDIM], dsm[192];
        posf[tid]       = g_feats[0][s * CDIM + tid];
        posf[tid + 256] = g_feats[0][s * CDIM + tid + 256];
        negf[tid]       = g_feats[1][s * CDIM + tid];
        negf[tid + 256] = g_feats[1][s * CDIM + tid + 256];
        __syncthreads();
        if (tid < 192) {
            int kind = tid / 64, j = tid % 64;
            const float* f = (kind == 2) ? negf : posf;
            const float* p = ((kind == 1) ? g_p[1] : g_p[0]) + j * CDIM;
            float d = 0.f;
            for (int c = 0; c < CDIM; c += 4) {
                float4 pv = *(const float4*)(p + c);
                d = fmaf(f[c], pv.x, fmaf(f[c+1], pv.y, fmaf(f[c+2], pv.z, fmaf(f[c+3], pv.w, d))));
            }
            dsm[tid] = d;
        }
        __syncthreads();
        if (tid == 0) {
            float mp = dsm[0];
            for (int j = 1; j < 64; j++) mp = fmaxf(mp, dsm[j]);
            float mb = dsm[64];
            for (int j = 65; j < 128; j++) mb = fmaxf(mb, dsm[j]);
            float mn = dsm[128];
            for (int j = 129; j < 192; j++) mn = fmaxf(mn, dsm[j]);
            float a1 = mp / TAU;
            float sum1 = 0.f;
            for (int j = 0; j < 64; j++) sum1 += expf(dsm[j] / TAU - a1);
            float aall = fmaxf(mp, mb) / TAU;
            float sum2 = 0.f;
            for (int j = 0; j < 128; j++) sum2 += expf(dsm[j] / TAU - aall);
            float info = (aall + logf(sum2)) - (a1 + logf(sum1));
            // exact-integer accumulation (order-independent, deterministic)
            const double SC = 4294967296.0;
            atomicAdd(&g_lossacc[0], (unsigned long long)(long long)__double2ll_rn((double)mp * SC));
            atomicAdd(&g_lossacc[1], (unsigned long long)(long long)__double2ll_rn((double)mn * SC));
            atomicAdd(&g_lossacc[2], (unsigned long long)(long long)__double2ll_rn((double)info * SC));
            __threadfence();
            int prev = atomicAdd(&g_losscnt, 1);
            if (prev == 255) {
                long long l0 = (long long)atomicAdd(&g_lossacc[0], 0ULL);
                long long l1 = (long long)atomicAdd(&g_lossacc[1], 0ULL);
                long long l2 = (long long)atomicAdd(&g_lossacc[2], 0ULL);
                const double INV = 1.0 / (4294967296.0 * 256.0);
                float mpm = (float)((double)l0 * INV);
                float mnm = (float)((double)l1 * INV);
                float mim = (float)((double)l2 * INV);
                out[0] = fmaxf(0.f, MARGIN + mnm - mpm) + 0.25f * mim;
            }
        }
    } else {
        // refined proto output: 128 blocks, 2 channels per thread
        int r = b - 256;
        int side = r >> 6, k = r & 63;
        const float* src = side ? bg : fg;
        float v0 = (1.0f - MBLEND) * src[k * CDIM + tid]       + MBLEND * g_p[side][k * CDIM + tid];
        float v1 = (1.0f - MBLEND) * src[k * CDIM + tid + 256] + MBLEND * g_p[side][k * CDIM + tid + 256];
        __shared__ float red[256];
        red[tid] = v0 * v0 + v1 * v1;   // == state after first tree step of original 512-tree
        __syncthreads();
        for (int o = 128; o > 0; o >>= 1) {
            if (tid < o) red[tid] += red[tid + o];
            __syncthreads();
        }
        float inv = 1.0f / fmaxf(sqrtf(red[0]), 1e-8f);
        out[1 + side * (KP * CDIM) + k * CDIM + tid]       = v0 * inv;
        out[1 + side * (KP * CDIM) + k * CDIM + tid + 256] = v1 * inv;
    }
}

// ---------------- launch: 9 graph nodes ----------------
extern "C" void kernel_launch(void* const* d_in, const int* in_sizes, int n_in,
                              void* d_out, int out_size) {
    const float* fg = (const float*)d_in[0];
    const float* bg = (const float*)d_in[1];
    const float* F  = (const float*)d_in[2];
    const float* M  = (const float*)d_in[3];
    float* out = (float*)d_out;

    cudaFuncSetAttribute(score_tc, cudaFuncAttributeMaxDynamicSharedMemorySize, SCORE_SMEM);

    prep_all<<<256, 256>>>(fg, bg);
    score_tc<<<NP / 128, 256, SCORE_SMEM>>>(F, M);
    pick16_kernel<<<2, 256>>>();
    collect_kernel<<<dim3(NP / 256, 2), 256>>>();
    rescore_kernel<<<dim3(CAP / 16, 2), 256>>>(F, M);
    select256_kernel<<<2, 256>>>();
    gather_kernel<<<dim3(NSEL, 2), 128>>>(F, fg, bg);
    refine_cluster<<<16, 512>>>();
    loss_final<<<384, 256>>>(fg, bg, out);
}

// round 17
// speedup vs baseline: 1.9577x; 1.9577x over previous
#include <cuda_runtime.h>
#include <cuda_bf16.h>
#include <math.h>

#define NP      147456      // 16*96*96
#define HW      9216        // 96*96
#define CDIM    512
#define KP      64          // protos per side
#define NSEL    256
#define NREF    10
#define TAU     0.07f
#define MARGIN  0.2f
#define MBLEND  0.3f

#define NCAND   2048        // approx-candidate target per side
#define CAP     4096        // candidate buffer cap (whole boundary bin included)

// ---------------- scratch ----------------
__device__ float     g_Wt[CDIM * 128];
__device__ unsigned  g_Wb16u[128 * 256];
__device__ float     g_score[2][NP];
__device__ unsigned  g_hist16[2][65536];
__device__ int       g_thr16[2];
__device__ int       g_ccnt[2];
__device__ int       g_cand[2][CAP];
__device__ float     g_cscore[2][CAP];
__device__ int       g_idx[2][NSEL];
__device__ float     g_feats[2][NSEL * CDIM];
__device__ float     g_p[2][KP * CDIM];
__device__ int       g_assign[2][NSEL];
__device__ unsigned long long g_lossacc[3];
__device__ int       g_losscnt;

// ---------------- helpers ----------------
__device__ __forceinline__ unsigned mapf(float x) {
    unsigned u = __float_as_uint(x);
    return (u & 0x80000000u) ? ~u : (u | 0x80000000u);
}
__device__ __forceinline__ unsigned pack_bf2(float lo, float hi) {
    unsigned r;
    asm("cvt.rn.bf16x2.f32 %0, %1, %2;" : "=r"(r) : "f"(hi), "f"(lo));
    return r;
}
__device__ __forceinline__ void mma16816(float* c, const unsigned* a, unsigned b0, unsigned b1) {
    asm volatile("mma.sync.aligned.m16n8k16.row.col.f32.bf16.bf16.f32 "
                 "{%0,%1,%2,%3}, {%4,%5,%6,%7}, {%8,%9}, {%0,%1,%2,%3};"
                 : "+f"(c[0]), "+f"(c[1]), "+f"(c[2]), "+f"(c[3])
                 : "r"(a[0]), "r"(a[1]), "r"(a[2]), "r"(a[3]), "r"(b0), "r"(b1));
}
__device__ __forceinline__ unsigned sptr(const void* p) {
    return (unsigned)__cvta_generic_to_shared(p);
}
__device__ __forceinline__ void cp16_cg(unsigned s, const void* g) {
    asm volatile("cp.async.cg.shared.global [%0], [%1], 16;" :: "r"(s), "l"(g));
}
__device__ __forceinline__ void cp16_ca(unsigned s, const void* g) {
    asm volatile("cp.async.ca.shared.global [%0], [%1], 16;" :: "r"(s), "l"(g));
}

// ---------------- kernel 1: fused prep (verified R16) ----------------
__global__ void prep_all(const float* __restrict__ fg, const float* __restrict__ bg) {
    int gid = blockIdx.x * 256 + threadIdx.x;   // 65536 threads
    ((unsigned*)&g_hist16[0][0])[gid] = 0u;
    ((unsigned*)&g_hist16[0][0])[gid + 65536] = 0u;
    if (gid < 2) g_ccnt[gid] = 0;
    if (gid < 3) g_lossacc[gid] = 0ULL;
    if (gid == 0) g_losscnt = 0;
    {
        int c = gid >> 7, j = gid & 127;
        float v = (j < KP) ? fg[j * CDIM + c] : bg[(j - KP) * CDIM + c];
        g_Wt[gid] = v;
    }
    if (gid < 32768) {
        int j = gid >> 8, cp = gid & 255;
        const float* src = (j < KP) ? (fg + j * CDIM) : (bg + (j - KP) * CDIM);
        g_Wb16u[gid] = pack_bf2(src[cp * 2], src[cp * 2 + 1]);
    }
}

// ---------------- kernel 2: approx score (bf16 TC) + fused hist16 (verified R16) ----------------
#define SCORE_SMEM (32768 + 20480 + 10240 + 512)
__global__ __launch_bounds__(256, 2) void score_tc(
    const float* __restrict__ F, const float* __restrict__ M) {
    extern __shared__ char smem_raw[];
    float*    Af32   = (float*)smem_raw;
    unsigned* Wst    = (unsigned*)(smem_raw + 32768);
    unsigned* As32   = (unsigned*)(smem_raw + 32768 + 20480);
    float*    normsh = (float*)(smem_raw + 63488);

    int tid = threadIdx.x, lane = tid & 31, w = tid >> 5;
    int wm = w >> 1, wn = w & 1;
    int gpix0 = blockIdx.x * 128;
    int n = gpix0 / HW, hw0 = gpix0 - n * HW;
    const float* Fb = F + (size_t)n * CDIM * HW + hw0;

    if (tid < 128) normsh[tid] = 0.f;

    float acc[2][8][4];
#pragma unroll
    for (int a = 0; a < 2; a++)
#pragma unroll
        for (int b = 0; b < 8; b++)
#pragma unroll
            for (int d = 0; d < 4; d++) acc[a][b][d] = 0.f;

    int px = tid & 127, half = tid >> 7;
    float mynrm = 0.f;

    auto issue_chunk = [&](int ic) {
        int buf = ic & 1;
        int c0 = ic * 32;
        float* Ad = Af32 + buf * (32 * 128);
#pragma unroll
        for (int j = 0; j < 4; j++) {
            int idx = tid + 256 * j;
            int r = idx >> 5, sg = idx & 31;
            cp16_cg(sptr(Ad + r * 128 + sg * 4),
                    Fb + (size_t)(c0 + r) * HW + sg * 4);
        }
        unsigned* Wd = Wst + buf * (128 * 20);
#pragma unroll
        for (int j = 0; j < 2; j++) {
            int idx = tid + 256 * j;
            int p = idx >> 2, sg = idx & 3;
            cp16_ca(sptr(Wd + p * 20 + sg * 4),
                    g_Wb16u + p * 256 + (c0 >> 1) + sg * 4);
        }
        asm volatile("cp.async.commit_group;");
    };

    issue_chunk(0);
    issue_chunk(1);

    int g = lane >> 2, t4 = lane & 3;
    for (int ic = 0; ic < 16; ic++) {
        int buf = ic & 1;
        if (ic < 15) asm volatile("cp.async.wait_group 1;");
        else         asm volatile("cp.async.wait_group 0;");
        __syncthreads();

        {
            const float* Asrc = Af32 + buf * (32 * 128);
#pragma unroll
            for (int kp = 0; kp < 8; kp++) {
                int k = (half * 8 + kp) * 2;
                float v0 = Asrc[k * 128 + px];
                float v1 = Asrc[(k + 1) * 128 + px];
                mynrm += v0 * v0 + v1 * v1;
                As32[px * 20 + half * 8 + kp] = pack_bf2(v0, v1);
            }
        }
        __syncthreads();

        {
            const unsigned* Ws = Wst + buf * (128 * 20);
#pragma unroll
            for (int k16 = 0; k16 < 2; k16++) {
                unsigned a[2][4];
#pragma unroll
                for (int mt = 0; mt < 2; mt++) {
                    int row = wm * 32 + mt * 16 + g;
                    int base = row * 20 + k16 * 8 + t4;
                    a[mt][0] = As32[base];
                    a[mt][1] = As32[base + 8 * 20];
                    a[mt][2] = As32[base + 4];
                    a[mt][3] = As32[base + 8 * 20 + 4];
                }
#pragma unroll
                for (int nt = 0; nt < 8; nt++) {
                    int pr = wn * 64 + nt * 8 + g;
                    int bb = pr * 20 + k16 * 8 + t4;
                    unsigned b0 = Ws[bb], b1 = Ws[bb + 4];
#pragma unroll
                    for (int mt = 0; mt < 2; mt++) mma16816(acc[mt][nt], a[mt], b0, b1);
                }
            }
        }
        __syncthreads();
        if (ic + 2 < 16) issue_chunk(ic + 2);
    }

    atomicAdd(&normsh[px], mynrm);
    __syncthreads();

#pragma unroll
    for (int mt = 0; mt < 2; mt++) {
#pragma unroll
        for (int h = 0; h < 2; h++) {
            float m = -1e30f;
#pragma unroll
            for (int nt = 0; nt < 8; nt++)
                m = fmaxf(m, fmaxf(acc[mt][nt][h * 2], acc[mt][nt][h * 2 + 1]));
            m = fmaxf(m, __shfl_xor_sync(0xFFFFFFFFu, m, 1));
            m = fmaxf(m, __shfl_xor_sync(0xFFFFFFFFu, m, 2));
            if ((lane & 3) == 0) {
                int p = wm * 32 + mt * 16 + h * 8 + g;
                float inv = 1.0f / fmaxf(sqrtf(normsh[p]), 1e-8f);
                float sim = m * inv;
                float mv = fminf(fmaxf(M[gpix0 + p], 0.f), 1.f);
                float d = 1.0f - sim;
                float sc = (wn == 0) ? d * mv : d * (1.0f - mv);
                g_score[wn][gpix0 + p] = sc;
                atomicAdd(&g_hist16[wn][mapf(sc) >> 16], 1u);   // fused hist16
            }
        }
    }
}

// ---------------- kernel 3: pick 16-bit threshold (verified R15/R16) ----------------
__global__ void pick16_kernel() {
    int side = blockIdx.x, tid = threadIdx.x;   // 256 threads
    __shared__ unsigned ps[256];
    __shared__ unsigned suf[256];
    __shared__ int sh_seg;

    {
        const uint4* h4 = (const uint4*)&g_hist16[side][tid * 256];
        unsigned s = 0;
#pragma unroll 16
        for (int i = 0; i < 64; i++) {
            uint4 v = h4[i];
            s += v.x + v.y + v.z + v.w;
        }
        ps[tid] = s;
    }
    __syncthreads();
    for (int o = 1; o < 256; o <<= 1) {
        unsigned add = (tid + o < 256) ? ps[tid + o] : 0u;
        __syncthreads();
        ps[tid] += add;
        __syncthreads();
    }
    if (ps[tid] >= (unsigned)NCAND && (tid == 255 || ps[tid + 1] < (unsigned)NCAND))
        sh_seg = tid;
    __syncthreads();
    int seg = sh_seg;
    unsigned segAbove = (seg == 255) ? 0u : ps[seg + 1];

    suf[tid] = g_hist16[side][seg * 256 + tid];
    __syncthreads();
    for (int o = 1; o < 256; o <<= 1) {
        unsigned add = (tid + o < 256) ? suf[tid + o] : 0u;
        __syncthreads();
        suf[tid] += add;
        __syncthreads();
    }
    unsigned need = (unsigned)NCAND - segAbove;
    if (suf[tid] >= need && (tid == 255 || suf[tid + 1] < need))
        g_thr16[side] = seg * 256 + tid;
}

// ---------------- kernel 4: collect candidates (thr16 superset, verified R16) ----------------
__global__ void collect_kernel() {
    int side = blockIdx.y;
    int i = blockIdx.x * 256 + threadIdx.x;
    unsigned key16 = mapf(g_score[side][i]) >> 16;
    if ((int)key16 >= g_thr16[side]) {
        int pos = atomicAdd(&g_ccnt[side], 1);
        if (pos < CAP) g_cand[side][pos] = i;
    }
}

// ---------------- kernel 5: exact FP32 rescore (16 cand/block, verified) ----------------
__global__ __launch_bounds__(256) void rescore_kernel(
    const float* __restrict__ F, const float* __restrict__ M) {
    int side = blockIdx.y;
    int s0 = blockIdx.x * 16;
    int tid = threadIdx.x, lane = tid & 31, w = tid >> 5;
    int cnt = min(g_ccnt[side], CAP);

    if (s0 >= cnt) {
        if (tid < 16) g_cscore[side][s0 + tid] = -3.0e38f;
        return;
    }

    __shared__ float fsh[16][CDIM];
    __shared__ float nrm[16];

#pragma unroll
    for (int h = 0; h < 2; h++) {
        int cslot = 2 * w + h;
        int s = s0 + cslot;
        bool valid = (s < cnt);
        int idx = g_cand[side][valid ? s : 0];
        int n = idx / HW, hw = idx - n * HW;
        const float* base = F + (size_t)n * CDIM * HW + hw;
        float partial = 0.f;
#pragma unroll
        for (int i = 0; i < 16; i++) {
            int c = lane + 32 * i;
            float v = base[(size_t)c * HW];
            fsh[cslot][c] = v;
            partial += v * v;
        }
#pragma unroll
        for (int o = 16; o > 0; o >>= 1)
            partial += __shfl_xor_sync(0xFFFFFFFFu, partial, o);
        if (lane == 0) nrm[cslot] = partial;
    }
    __syncthreads();

    int half = lane >> 4, l16 = lane & 15;
    int cslot = 2 * w + half;
    const float* Wb = g_Wt + side * 64 + l16 * 4;
    float d0 = 0.f, d1 = 0.f, d2 = 0.f, d3 = 0.f;
#pragma unroll 4
    for (int c = 0; c < CDIM; c++) {
        float f = fsh[cslot][c];
        float4 wv = *(const float4*)(Wb + (size_t)c * 128);
        d0 = fmaf(f, wv.x, d0);
        d1 = fmaf(f, wv.y, d1);
        d2 = fmaf(f, wv.z, d2);
        d3 = fmaf(f, wv.w, d3);
    }
    float m = fmaxf(fmaxf(d0, d1), fmaxf(d2, d3));
#pragma unroll
    for (int o = 8; o > 0; o >>= 1)
        m = fmaxf(m, __shfl_xor_sync(0xFFFFFFFFu, m, o));
    if (l16 == 0) {
        int s = s0 + cslot;
        bool valid = (s < cnt);
        float val = -3.0e38f;
        if (valid) {
            int idx = g_cand[side][s];
            float inv = 1.0f / fmaxf(sqrtf(nrm[cslot]), 1e-8f);
            float sim = m * inv;
            float mv = fminf(fmaxf(M[idx], 0.f), 1.f);
            val = (side == 0) ? (1.0f - sim) * mv : (1.0f - sim) * (1.0f - mv);
        }
        g_cscore[side][s] = val;
    }
}

// ---------------- kernel 6: exact top-256 among candidates (verified) ----------------
__global__ void select256_kernel() {
    int side = blockIdx.x, tid = threadIdx.x;   // 256 threads
    const float* sc = g_cscore[side];
    const int* cd = g_cand[side];
    __shared__ unsigned hist[256];
    __shared__ unsigned suf[256];
    __shared__ unsigned sh_pfx, sh_dmask;
    __shared__ int sh_krem, gcnt, tcnt;
    __shared__ int glist[NSEL];
    __shared__ int ties[CAP];

    if (tid == 0) { sh_pfx = 0; sh_dmask = 0; sh_krem = NSEL; }
    __syncthreads();
    for (int shift = 24; shift >= 0; shift -= 8) {
        hist[tid] = 0;
        __syncthreads();
        unsigned dm = sh_dmask, pf = sh_pfx;
        for (int i = tid; i < CAP; i += 256) {
            unsigned key = mapf(sc[i]);
            if ((key & dm) == pf) atomicAdd(&hist[(key >> shift) & 255], 1u);
        }
        __syncthreads();
        suf[tid] = hist[tid];
        __syncthreads();
        for (int o = 1; o < 256; o <<= 1) {
            unsigned add = (tid + o < 256) ? suf[tid + o] : 0u;
            __syncthreads();
            suf[tid] += add;
            __syncthreads();
        }
        unsigned kr = (unsigned)sh_krem;
        if (suf[tid] >= kr && (tid == 255 || suf[tid + 1] < kr)) {
            sh_krem = (int)kr - (int)((tid == 255) ? 0u : suf[tid + 1]);
            sh_pfx   = sh_pfx | ((unsigned)tid << shift);
            sh_dmask = sh_dmask | (0xFFu << shift);
        }
        __syncthreads();
    }
    if (tid == 0) { gcnt = 0; tcnt = 0; }
    __syncthreads();
    unsigned thr = sh_pfx;
    for (int i = tid; i < CAP; i += 256) {
        unsigned key = mapf(sc[i]);
        if (key > thr) {
            int p = atomicAdd(&gcnt, 1);
            if (p < NSEL) glist[p] = cd[i];
        } else if (key == thr) {
            int p = atomicAdd(&tcnt, 1);
            if (p < CAP) ties[p] = cd[i];
        }
    }
    __syncthreads();
    int G = min(gcnt, NSEL);
    for (int e = tid; e < G; e += 256) {
        int pe = glist[e], r = 0;
        for (int j = 0; j < G; j++) r += (glist[j] < pe);
        g_idx[side][r] = pe;
    }
    int need = NSEL - G;
    int T = min(tcnt, CAP);
    for (int e = tid; e < T; e += 256) {
        int pe = ties[e], r = 0;
        for (int j = 0; j < T; j++) r += (ties[j] < pe);
        if (r < need) g_idx[side][G + r] = pe;
    }
}

// ---------------- kernel 7: gather + normalize + fused proto init (verified R16) ----------------
__global__ void gather_kernel(const float* __restrict__ F,
                              const float* __restrict__ fg, const float* __restrict__ bg) {
    int s = blockIdx.x, side = blockIdx.y;
    int idx = g_idx[side][s];
    int n = idx / HW, hw = idx - n * HW;
    const float* base = F + (size_t)n * CDIM * HW + hw;
    int tid = threadIdx.x;  // 128
    float v[4], ss = 0.f;
#pragma unroll
    for (int i = 0; i < 4; i++) {
        int c = tid + i * 128;
        v[i] = base[(size_t)c * HW];
        ss += v[i] * v[i];
    }
#pragma unroll
    for (int o = 16; o > 0; o >>= 1) ss += __shfl_xor_sync(0xFFFFFFFFu, ss, o);
    __shared__ float wsum[4];
    if ((tid & 31) == 0) wsum[tid >> 5] = ss;
    __syncthreads();
    float inv = 1.0f / fmaxf(sqrtf(wsum[0] + wsum[1] + wsum[2] + wsum[3]), 1e-8f);
#pragma unroll
    for (int i = 0; i < 4; i++)
        g_feats[side][s * CDIM + tid + i * 128] = v[i] * inv;
    if (s < KP) {
        const float* src = side ? bg : fg;
#pragma unroll
        for (int i = 0; i < 4; i++)
            g_p[side][s * CDIM + tid + i * 128] = src[s * CDIM + tid + i * 128];
    }
}

// ---------------- refinement (R11/R15-verified structure) ----------------
__global__ void assign_kernel() {
    int side = blockIdx.y;
    int s0 = blockIdx.x * 8;
    __shared__ float fsm[8 * CDIM];
    __shared__ float dsm[8][KP];
    int tid = threadIdx.x;  // 256
    const float4* src = (const float4*)(g_feats[side] + s0 * CDIM);
#pragma unroll
    for (int i = 0; i < 4; i++)
        ((float4*)fsm)[tid + 256 * i] = src[tid + 256 * i];
    __syncthreads();
    int j = tid & 63, sg = tid >> 6;
    const float* pj = g_p[side] + j * CDIM;
    const float* fa = fsm + (sg * 2) * CDIM;
    const float* fb = fa + CDIM;
    float d0 = 0.f, d1 = 0.f;
    for (int c = 0; c < CDIM; c += 4) {
        float4 pv = *(const float4*)(pj + c);
        float4 av = *(const float4*)(fa + c);
        float4 bv = *(const float4*)(fb + c);
        d0 = fmaf(av.x, pv.x, fmaf(av.y, pv.y, fmaf(av.z, pv.z, fmaf(av.w, pv.w, d0))));
        d1 = fmaf(bv.x, pv.x, fmaf(bv.y, pv.y, fmaf(bv.z, pv.z, fmaf(bv.w, pv.w, d1))));
    }
    dsm[sg * 2][j] = d0;
    dsm[sg * 2 + 1][j] = d1;
    __syncthreads();
    if (tid < 8) {
        float best = dsm[tid][0];
        int bj = 0;
        for (int jj = 1; jj < KP; jj++) {
            float v = dsm[tid][jj];
            if (v > best) { best = v; bj = jj; }
        }
        g_assign[side][s0 + tid] = bj;
    }
}

__global__ void update_kernel(float step) {
    int k = blockIdx.x, side = blockIdx.y;
    int tid = threadIdx.x;  // 256
    __shared__ int asg[NSEL];
    __shared__ float red[256];
    asg[tid] = g_assign[side][tid];
    __syncthreads();
    int c = tid;
    float s0 = 0.f, s1 = 0.f;
    int cnt = 0;
    for (int s = 0; s < NSEL; s++) {
        if (asg[s] == k) {
            cnt++;
            const float* f = g_feats[side] + s * CDIM;
            s0 += f[c];
            s1 += f[c + 256];
        }
    }
    float denom = fmaxf((float)cnt, 1.0f);
    float p0 = g_p[side][k * CDIM + c];
    float p1 = g_p[side][k * CDIM + c + 256];
    float v0 = (1.0f - step) * p0 + step * (s0 / denom);
    float v1 = (1.0f - step) * p1 + step * (s1 / denom);
    red[tid] = v0 * v0 + v1 * v1;
    __syncthreads();
    for (int o = 128; o > 0; o >>= 1) {
        if (tid < o) red[tid] += red[tid + o];
        __syncthreads();
    }
    float inv = 1.0f / fmaxf(sqrtf(red[0]), 1e-8f);
    if (cnt > 0) {
        g_p[side][k * CDIM + c]       = v0 * inv;
        g_p[side][k * CDIM + c + 256] = v1 * inv;
    }
}

// ---------------- kernel: loss + refined output + integer finalize (verified R16) ----------------
__global__ __launch_bounds__(256) void loss_final(
    const float* __restrict__ fg, const float* __restrict__ bg,
    float* __restrict__ out) {
    int b = blockIdx.x, tid = threadIdx.x;

    if (b < 256) {
        int s = b;
        __shared__ float posf[CDIM], negf[CDIM], dsm[192];
        posf[tid]       = g_feats[0][s * CDIM + tid];
        posf[tid + 256] = g_feats[0][s * CDIM + tid + 256];
        negf[tid]       = g_feats[1][s * CDIM + tid];
        negf[tid + 256] = g_feats[1][s * CDIM + tid + 256];
        __syncthreads();
        if (tid < 192) {
            int kind = tid / 64, j = tid % 64;
            const float* f = (kind == 2) ? negf : posf;
            const float* p = ((kind == 1) ? g_p[1] : g_p[0]) + j * CDIM;
            float d = 0.f;
            for (int c = 0; c < CDIM; c += 4) {
                float4 pv = *(const float4*)(p + c);
                d = fmaf(f[c], pv.x, fmaf(f[c+1], pv.y, fmaf(f[c+2], pv.z, fmaf(f[c+3], pv.w, d))));
            }
            dsm[tid] = d;
        }
        __syncthreads();
        if (tid == 0) {
            float mp = dsm[0];
            for (int j = 1; j < 64; j++) mp = fmaxf(mp, dsm[j]);
            float mb = dsm[64];
            for (int j = 65; j < 128; j++) mb = fmaxf(mb, dsm[j]);
            float mn = dsm[128];
            for (int j = 129; j < 192; j++) mn = fmaxf(mn, dsm[j]);
            float a1 = mp / TAU;
            float sum1 = 0.f;
            for (int j = 0; j < 64; j++) sum1 += expf(dsm[j] / TAU - a1);
            float aall = fmaxf(mp, mb) / TAU;
            float sum2 = 0.f;
            for (int j = 0; j < 128; j++) sum2 += expf(dsm[j] / TAU - aall);
            float info = (aall + logf(sum2)) - (a1 + logf(sum1));
            const double SC = 4294967296.0;
            atomicAdd(&g_lossacc[0], (unsigned long long)(long long)__double2ll_rn((double)mp * SC));
            atomicAdd(&g_lossacc[1], (unsigned long long)(long long)__double2ll_rn((double)mn * SC));
            atomicAdd(&g_lossacc[2], (unsigned long long)(long long)__double2ll_rn((double)info * SC));
            __threadfence();
            int prev = atomicAdd(&g_losscnt, 1);
            if (prev == 255) {
                long long l0 = (long long)atomicAdd(&g_lossacc[0], 0ULL);
                long long l1 = (long long)atomicAdd(&g_lossacc[1], 0ULL);
                long long l2 = (long long)atomicAdd(&g_lossacc[2], 0ULL);
                const double INV = 1.0 / (4294967296.0 * 256.0);
                float mpm = (float)((double)l0 * INV);
                float mnm = (float)((double)l1 * INV);
                float mim = (float)((double)l2 * INV);
                out[0] = fmaxf(0.f, MARGIN + mnm - mpm) + 0.25f * mim;
            }
        }
    } else {
        int r = b - 256;
        int side = r >> 6, k = r & 63;
        const float* src = side ? bg : fg;
        float v0 = (1.0f - MBLEND) * src[k * CDIM + tid]       + MBLEND * g_p[side][k * CDIM + tid];
        float v1 = (1.0f - MBLEND) * src[k * CDIM + tid + 256] + MBLEND * g_p[side][k * CDIM + tid + 256];
        __shared__ float red[256];
        red[tid] = v0 * v0 + v1 * v1;
        __syncthreads();
        for (int o = 128; o > 0; o >>= 1) {
            if (tid < o) red[tid] += red[tid + o];
            __syncthreads();
        }
        float inv = 1.0f / fmaxf(sqrtf(red[0]), 1e-8f);
        out[1 + side * (KP * CDIM) + k * CDIM + tid]       = v0 * inv;
        out[1 + side * (KP * CDIM) + k * CDIM + tid + 256] = v1 * inv;
    }
}

// ---------------- launch: 28 graph nodes ----------------
extern "C" void kernel_launch(void* const* d_in, const int* in_sizes, int n_in,
                              void* d_out, int out_size) {
    const float* fg = (const float*)d_in[0];
    const float* bg = (const float*)d_in[1];
    const float* F  = (const float*)d_in[2];
    const float* M  = (const float*)d_in[3];
    float* out = (float*)d_out;

    cudaFuncSetAttribute(score_tc, cudaFuncAttributeMaxDynamicSharedMemorySize, SCORE_SMEM);

    prep_all<<<256, 256>>>(fg, bg);
    score_tc<<<NP / 128, 256, SCORE_SMEM>>>(F, M);
    pick16_kernel<<<2, 256>>>();
    collect_kernel<<<dim3(NP / 256, 2), 256>>>();
    rescore_kernel<<<dim3(CAP / 16, 2), 256>>>(F, M);
    select256_kernel<<<2, 256>>>();
    gather_kernel<<<dim3(NSEL, 2), 128>>>(F, fg, bg);
    for (int it = 0; it < NREF; it++) {
        float step = 0.1f / (1.0f + 0.5f * (float)it);
        assign_kernel<<<dim3(NSEL / 8, 2), 256>>>();
        update_kernel<<<dim3(KP, 2), 256>>>(step);
    }
    loss_final<<<384, 256>>>(fg, bg, out);
}